// round 7
// baseline (speedup 1.0000x reference)
#include <cuda_runtime.h>

// Problem constants
#define NPIX   65536          // 256*256
#define DH     64             // histogram bins
#define PB     16             // pixels staged per round
#define NCHUNK 18             // pixel chunks per (img,b) -> 16*18 = 288 CTAs (2/SM)
#define CPX    ((NPIX + NCHUNK - 1) / NCHUNK)
#define HISTN  (2 * 8 * 3 * DH * DH)

// Scratch (allocation-free rule: __device__ globals)
__device__ float g_hist[HISTN];   // [img][b][ch][64][64]
__device__ float g_hn[8];

__device__ __forceinline__ float frcp(float x) {
    float r; asm("rcp.approx.f32 %0, %1;" : "=f"(r) : "f"(x)); return r;
}
__device__ __forceinline__ float fsqrt_ap(float x) {
    float r; asm("sqrt.approx.f32 %0, %1;" : "=f"(r) : "f"(x)); return r;
}
__device__ __forceinline__ float plo(unsigned long long v) {
    return __uint_as_float((unsigned int)(v & 0xffffffffull));
}
__device__ __forceinline__ float phi(unsigned long long v) {
    return __uint_as_float((unsigned int)(v >> 32));
}

#define FFMA2(acc, a, b) asm("fma.rn.f32x2 %0, %1, %2, %0;" : "+l"(acc) : "l"(a), "l"(b))

// ---------------------------------------------------------------------------
// Kernel 0: zero a slice of the histogram scratch (3 launches keep hist_kernel
// at global launch index 5 for the ncu -s 5 -c 1 capture).
// ---------------------------------------------------------------------------
__global__ void zero_kernel(int off) {
    int i = off + blockIdx.x * blockDim.x + threadIdx.x;
    if (i < HISTN) g_hist[i] = 0.0f;
}

// ---------------------------------------------------------------------------
// Kernel 1: histogram accumulation.
// 256-thread CTAs, 2 CTAs/SM. SQUARE register tiles: warp w = (Wr, Wc) with
// Wr = w>>2 (2 row-halves), Wc = w&3 (4 col-quarters); lane l = (lr, lc) with
// lr = l&7, lc = l>>3. Each lane owns rows {32Wr+4lr .. +3} x cols
// {16Wc+4lc .. +3} for all 3 channels -> 24 packed f32x2 accumulators.
// Per warp-pixel stage C: 4 LDS.128 (dup rows U,Vi) + 2 LDS.128 (natural col
// quads V,W) = 12 L1 slots for 24 FFMA2 (was 20 slots with the 8x2 tiling).
//
// With U = iy*rbf(ur), Vi = iy*rbf(vr), V = rbf(vr), W = rbf(lg-lb):
//   accR[r][c] = sum U[r]*V[c]  = hist_r[r][c]
//   accG[r][c] = sum U[r]*W[c]  = hist_g[63-r][c]     (reverse rows at writeout)
//   accB[r][c] = sum Vi[r]*W[c] = hist_b[63-r][63-c]  (reverse both at writeout)
//
// Single __syncthreads per 16-pixel round (double-buffered SMEM; Stage B fills
// buf[nxt] while Stage C consumes buf[cur]; pixel scalars broadcast in-warp).
// ---------------------------------------------------------------------------
__global__ void __launch_bounds__(256, 2)
hist_kernel(const float* __restrict__ x, const float* __restrict__ y) {
    int combo = blockIdx.x / NCHUNK;
    int chunk = blockIdx.x % NCHUNK;
    int img = combo >> 3;
    int b   = combo & 7;
    const float* src = img ? y : x;
    const float* pr  = src + (size_t)(b * 3 + 0) * NPIX;
    const float* pg  = src + (size_t)(b * 3 + 1) * NPIX;
    const float* pbl = src + (size_t)(b * 3 + 2) * NPIX;

    int cs = chunk * CPX;
    int ce = cs + CPX; if (ce > NPIX) ce = NPIX;

    // Double-buffered SMEM. "2" arrays hold each value DUPLICATED (f32x2 pairs).
    __shared__ float s_su2 [2][PB][128];  // U  = iy*rbf(ur), duplicated
    __shared__ float s_svi2[2][PB][128];  // Vi = iy*rbf(vr), duplicated
    __shared__ float s_sv  [2][PB][64];   // V  = rbf(vr), natural
    __shared__ float s_w   [2][PB][64];   // W  = rbf(lg-lb), natural

    const int tid = threadIdx.x;
    const int w   = tid >> 5;          // warp 0..7
    const int l   = tid & 31;
    const int Wr  = w >> 2;            // 0..1 -> row half
    const int Wc  = w & 3;             // 0..3 -> col quarter
    const int lr  = l & 7;             // 0..7 -> 4-row group within half
    const int lc  = l >> 3;            // 0..3 -> 4-col group within quarter
    const int row0 = 32 * Wr + 4 * lr; // first of this lane's 4 rows
    const int col0 = 16 * Wc + 4 * lc; // first of this lane's 4 cols
    const int p   = tid >> 4;          // pixel-in-round this thread evaluates (Stage B)
    const int i0  = tid & 15;          // bin base (bins i0, i0+16, i0+32, i0+48)
    const bool owner = (i0 == 0);
    const int srcln  = l & 16;         // owner lane within warp (0 or 16)

    // acc[ch][r][cp]: r = row index 0..3, cp = col pair 0..1
    unsigned long long accR[4][2], accG[4][2], accB[4][2];
#pragma unroll
    for (int k = 0; k < 4; k++)
#pragma unroll
        for (int m = 0; m < 2; m++) { accR[k][m] = 0ull; accG[k][m] = 0ull; accB[k][m] = 0ull; }

    const int nr = (ce - cs + PB - 1) / PB;

    // Owner-lane prefetch registers; fr = -1 marks an invalid (pad) pixel.
    int pn = cs + p;
    float fr = -1.f, fg = 0.f, fb = 0.f;
    if (owner && pn < ce) { fr = pr[pn]; fg = pg[pn]; fb = pbl[pn]; }

    // Stage B: evaluate RBF rows for this thread's pixel into buffer nb.
    auto stageB = [&](int nb) {
        float r0 = __shfl_sync(0xffffffffu, fr, srcln);
        float g0 = __shfl_sync(0xffffffffu, fg, srcln);
        float b0 = __shfl_sync(0xffffffffu, fb, srcln);
        bool valid = (r0 >= 0.f);
        float r  = valid ? r0 + 1e-6f : 1.0f;
        float g  = valid ? g0 + 1e-6f : 1.0f;
        float bb = valid ? b0 + 1e-6f : 1.0f;
        float lr_ = __logf(r), lg_ = __logf(g), lb_ = __logf(bb);
        float ur = lr_ - lg_;
        float vr = lr_ - lb_;
        float wv = lg_ - lb_;
        float iy = valid ? fsqrt_ap(fmaf(r, r, fmaf(g, g, bb * bb))) : 0.f;
#pragma unroll
        for (int k = 0; k < 4; k++) {
            int i = i0 + 16 * k;
            float c50 = fmaf((float)i, 300.0f / 63.0f, -150.0f);  // 50 * center_i
            float tu = fmaf(ur, 50.0f, -c50);
            float su = iy * frcp(fmaf(tu, tu, 1.0f));             // U
            float tv = fmaf(vr, 50.0f, -c50);
            float sv = frcp(fmaf(tv, tv, 1.0f));                  // V
            float tw = fmaf(wv, 50.0f, -c50);
            float sw = frcp(fmaf(tw, tw, 1.0f));                  // W
            s_sv[nb][p][i] = sv;
            s_w [nb][p][i] = sw;
            *(float2*)&s_su2 [nb][p][2 * i] = make_float2(su, su);
            float vi = iy * sv;
            *(float2*)&s_svi2[nb][p][2 * i] = make_float2(vi, vi);  // Vi
        }
    };

    // Prologue: fill buffer 0, prefetch round 1.
    stageB(0);
    pn += PB; fr = -1.f;
    if (owner && pn < ce) { fr = pr[pn]; fg = pg[pn]; fb = pbl[pn]; }
    __syncthreads();

    // Lane-fixed bases: dup row arrays at float 2*row0 = 8*lr + 64*Wr... (2*(32Wr+4lr))
    const float* su2b  = &s_su2 [0][0][0] + 2 * row0;   // 16B-aligned (row0 mult of 4)
    const float* svi2b = &s_svi2[0][0][0] + 2 * row0;
    const float* svb   = &s_sv  [0][0][0] + col0;       // natural quad, 16B-aligned
    const float* wb    = &s_w   [0][0][0] + col0;

    for (int it = 0; it < nr; it++) {
        int cur = it & 1;
        if (it + 1 < nr) {
            stageB(cur ^ 1);
            pn += PB; fr = -1.f;
            if (owner && pn < ce) { fr = pr[pn]; fg = pg[pn]; fb = pbl[pn]; }
        }

        const float* su2p  = su2b  + cur * (PB * 128);
        const float* svi2p = svi2b + cur * (PB * 128);
        const float* svp   = svb   + cur * (PB * 64);
        const float* wp    = wb    + cur * (PB * 64);

        // Stage C: 16 pixels; 6 LDS.128 + 24 FFMA2 per pixel.
#pragma unroll
        for (int q = 0; q < PB; q++) {
            ulonglong2 u01 = *(const ulonglong2*)(su2p  + q * 128);      // dup U rows r0,r0+1
            ulonglong2 u23 = *(const ulonglong2*)(su2p  + q * 128 + 4);  // dup U rows r0+2,r0+3
            ulonglong2 x01 = *(const ulonglong2*)(svi2p + q * 128);      // dup Vi
            ulonglong2 x23 = *(const ulonglong2*)(svi2p + q * 128 + 4);
            ulonglong2 cv  = *(const ulonglong2*)(svp + q * 64);         // V[c0..c0+3] natural
            ulonglong2 cw  = *(const ulonglong2*)(wp  + q * 64);         // W[c0..c0+3] natural

            unsigned long long rU [4] = { u01.x, u01.y, u23.x, u23.y };
            unsigned long long rVi[4] = { x01.x, x01.y, x23.x, x23.y };
            unsigned long long cV [2] = { cv.x, cv.y };
            unsigned long long cW [2] = { cw.x, cw.y };

#pragma unroll
            for (int k = 0; k < 4; k++) {
#pragma unroll
                for (int m = 0; m < 2; m++) {
                    FFMA2(accR[k][m], rU[k],  cV[m]);
                    FFMA2(accG[k][m], rU[k],  cW[m]);
                    FFMA2(accB[k][m], rVi[k], cW[m]);
                }
            }
        }
        __syncthreads();
    }

    // ---- Writeout: atomic reduce into global hist (reversals applied here) ----
    size_t basec = ((size_t)(img * 8 + b)) * 3 * 4096;
    float* hR = g_hist + basec;
    float* hG = g_hist + basec + 4096;
    float* hB = g_hist + basec + 8192;
#pragma unroll
    for (int k = 0; k < 4; k++) {
        int row  = row0 + k;
        int rofw = row * 64;              // forward row offset (R)
        int rofr = (63 - row) * 64;       // reversed row offset (G, B)
#pragma unroll
        for (int m = 0; m < 2; m++) {
            int c0 = col0 + 2 * m;
            atomicAdd(hR + rofw + c0,      plo(accR[k][m]));
            atomicAdd(hR + rofw + c0 + 1,  phi(accR[k][m]));
            atomicAdd(hG + rofr + c0,      plo(accG[k][m]));
            atomicAdd(hG + rofr + c0 + 1,  phi(accG[k][m]));
            atomicAdd(hB + rofr + 63 - c0, plo(accB[k][m]));
            atomicAdd(hB + rofr + 62 - c0, phi(accB[k][m]));
        }
    }
}

// ---------------------------------------------------------------------------
// Kernel 2: per-batch normalize + Hellinger-style distance
// ---------------------------------------------------------------------------
__global__ void loss_kernel() {
    int b = blockIdx.x;                     // 0..7
    const float* hx = g_hist + (size_t)b * 12288;         // img 0
    const float* hy = g_hist + (size_t)(8 + b) * 12288;   // img 1
    __shared__ float red[256];
    int tid = threadIdx.x;

    float sx = 0.f, sy = 0.f;
    for (int i = tid; i < 12288; i += 256) { sx += hx[i]; sy += hy[i]; }

    red[tid] = sx; __syncthreads();
    for (int s = 128; s > 0; s >>= 1) { if (tid < s) red[tid] += red[tid + s]; __syncthreads(); }
    float Tx = red[0]; __syncthreads();

    red[tid] = sy; __syncthreads();
    for (int s = 128; s > 0; s >>= 1) { if (tid < s) red[tid] += red[tid + s]; __syncthreads(); }
    float Ty = red[0]; __syncthreads();

    float ivx = 1.0f / Tx, ivy = 1.0f / Ty;
    float acc = 0.f;
    for (int i = tid; i < 12288; i += 256) {
        float d = sqrtf(hy[i] * ivy) - sqrtf(hx[i] * ivx);
        acc = fmaf(d, d, acc);
    }
    red[tid] = acc; __syncthreads();
    for (int s = 128; s > 0; s >>= 1) { if (tid < s) red[tid] += red[tid + s]; __syncthreads(); }
    if (tid == 0) g_hn[b] = sqrtf(red[0] * 0.5f);
}

// ---------------------------------------------------------------------------
// Kernel 3: mean over batch
// ---------------------------------------------------------------------------
__global__ void final_kernel(float* out) {
    if (threadIdx.x == 0) {
        float s = 0.f;
#pragma unroll
        for (int i = 0; i < 8; i++) s += g_hn[i];
        out[0] = s * 0.125f;
    }
}

// ---------------------------------------------------------------------------
extern "C" void kernel_launch(void* const* d_in, const int* in_sizes, int n_in,
                              void* d_out, int out_size) {
    const float* x = (const float*)d_in[0];
    const float* y = (const float*)d_in[1];

    const int SLICE = (HISTN + 2) / 3;
    zero_kernel<<<(SLICE + 255) / 256, 256>>>(0);
    zero_kernel<<<(SLICE + 255) / 256, 256>>>(SLICE);
    zero_kernel<<<(SLICE + 255) / 256, 256>>>(2 * SLICE);
    hist_kernel<<<16 * NCHUNK, 256>>>(x, y);
    loss_kernel<<<8, 256>>>();
    final_kernel<<<1, 32>>>((float*)d_out);
}

// round 9
// speedup vs baseline: 1.5900x; 1.5900x over previous
#include <cuda_runtime.h>

// Problem constants
#define NPIX   65536          // 256*256
#define DH     64             // histogram bins
#define PB     8              // pixels staged per round (8 px x 16 thr = 128)
#define NCHUNK 27             // pixel chunks per (img,b) -> 16*27 = 432 CTAs (~3/SM)
#define CPX    ((NPIX + NCHUNK - 1) / NCHUNK)
#define HISTN  (2 * 8 * 3 * DH * DH)

// Scratch (allocation-free rule: __device__ globals)
__device__ float g_hist[HISTN];   // [img][b][ch][64][64]
__device__ float g_hn[8];

__device__ __forceinline__ float frcp(float x) {
    float r; asm("rcp.approx.f32 %0, %1;" : "=f"(r) : "f"(x)); return r;
}
__device__ __forceinline__ float fsqrt_ap(float x) {
    float r; asm("sqrt.approx.f32 %0, %1;" : "=f"(r) : "f"(x)); return r;
}
__device__ __forceinline__ float plo(unsigned long long v) {
    return __uint_as_float((unsigned int)(v & 0xffffffffull));
}
__device__ __forceinline__ float phi(unsigned long long v) {
    return __uint_as_float((unsigned int)(v >> 32));
}

#define FFMA2(acc, a, b) asm("fma.rn.f32x2 %0, %1, %2, %0;" : "+l"(acc) : "l"(a), "l"(b))

// ---------------------------------------------------------------------------
// Kernel 0: zero a slice of the histogram scratch (3 launches keep hist_kernel
// at global launch index 5 for the ncu -s 5 -c 1 capture).
// ---------------------------------------------------------------------------
__global__ void zero_kernel(int off) {
    int i = off + blockIdx.x * blockDim.x + threadIdx.x;
    if (i < HISTN) g_hist[i] = 0.0f;
}

// ---------------------------------------------------------------------------
// Kernel 1: histogram accumulation.
// 128-thread CTAs (4 warps), 3 CTAs/SM. The 4 warps jointly cover the full
// 64x64 hist: warp wg (0..3) x lane (rg=l>>3, cg=l&7) owns rows
// {16wg+4rg .. +3} x cols {8cg .. 8cg+7} -> per-lane tile 4x8, i.e.
// 48 packed f32x2 accumulators across the 3 channels; 48 FFMA2 per pixel fed
// by 8 LDS.128 (2.67 B/FFMA2 -- 2.25x better than the R6 ratio).
// Row-dup loads: 4 distinct addrs 32B apart within one 128B line (conflict-
// free). Col loads: 8 distinct 16B quads (2 inherent phases).
//
// With U = iy*rbf(ur), Vi = iy*rbf(vr), V = rbf(vr), W = rbf(lg-lb):
//   accR[r][c] = sum U[r]*V[c]  = hist_r[r][c]
//   accG[r][c] = sum U[r]*W[c]  = hist_g[63-r][c]     (reverse rows at writeout)
//   accB[r][c] = sum Vi[r]*W[c] = hist_b[63-r][63-c]  (reverse both at writeout)
//
// Single __syncthreads per 8-pixel round (double-buffered SMEM; Stage B fills
// buf[nxt] while Stage C consumes buf[cur]; pixel scalars broadcast in-warp).
// ---------------------------------------------------------------------------
__global__ void __launch_bounds__(128, 3)
hist_kernel(const float* __restrict__ x, const float* __restrict__ y) {
    int combo = blockIdx.x / NCHUNK;
    int chunk = blockIdx.x % NCHUNK;
    int img = combo >> 3;
    int b   = combo & 7;
    const float* src = img ? y : x;
    const float* pr  = src + (size_t)(b * 3 + 0) * NPIX;
    const float* pg  = src + (size_t)(b * 3 + 1) * NPIX;
    const float* pbl = src + (size_t)(b * 3 + 2) * NPIX;

    int cs = chunk * CPX;
    int ce = cs + CPX; if (ce > NPIX) ce = NPIX;

    // Double-buffered SMEM. "2" arrays hold each value DUPLICATED (f32x2 pairs).
    __shared__ float s_su2 [2][PB][128];  // U  = iy*rbf(ur), duplicated
    __shared__ float s_svi2[2][PB][128];  // Vi = iy*rbf(vr), duplicated
    __shared__ float s_sv  [2][PB][64];   // V  = rbf(vr), natural
    __shared__ float s_w   [2][PB][64];   // W  = rbf(lg-lb), natural

    const int tid = threadIdx.x;
    const int wg  = tid >> 5;          // warp 0..3
    const int l   = tid & 31;
    const int rg  = l >> 3;            // 0..3
    const int cg  = l & 7;             // 0..7
    const int row0 = 16 * wg + 4 * rg; // this lane's 4 rows
    const int col0 = 8 * cg;           // this lane's 8 cols
    const int p   = tid >> 4;          // pixel-in-round this thread evaluates (Stage B)
    const int i0  = tid & 15;          // bin base (bins i0, i0+16, i0+32, i0+48)
    const bool owner = (i0 == 0);
    const int srcln  = l & 16;         // owner lane within warp (0 or 16)

    // acc[r][cp]: r = 0..3, cp = col pair 0..3
    unsigned long long accR[4][4], accG[4][4], accB[4][4];
#pragma unroll
    for (int k = 0; k < 4; k++)
#pragma unroll
        for (int m = 0; m < 4; m++) { accR[k][m] = 0ull; accG[k][m] = 0ull; accB[k][m] = 0ull; }

    const int nr = (ce - cs + PB - 1) / PB;

    // Owner-lane prefetch registers; fr = -1 marks an invalid (pad) pixel.
    int pn = cs + p;
    float fr = -1.f, fg = 0.f, fb = 0.f;
    if (owner && pn < ce) { fr = pr[pn]; fg = pg[pn]; fb = pbl[pn]; }

    // Stage B: evaluate RBF rows for this thread's pixel into buffer nb.
    auto stageB = [&](int nb) {
        float r0 = __shfl_sync(0xffffffffu, fr, srcln);
        float g0 = __shfl_sync(0xffffffffu, fg, srcln);
        float b0 = __shfl_sync(0xffffffffu, fb, srcln);
        bool valid = (r0 >= 0.f);
        float r  = valid ? r0 + 1e-6f : 1.0f;
        float g  = valid ? g0 + 1e-6f : 1.0f;
        float bb = valid ? b0 + 1e-6f : 1.0f;
        float lr_ = __logf(r), lg_ = __logf(g), lb_ = __logf(bb);
        float ur = lr_ - lg_;
        float vr = lr_ - lb_;
        float wv = lg_ - lb_;
        float iy = valid ? fsqrt_ap(fmaf(r, r, fmaf(g, g, bb * bb))) : 0.f;
#pragma unroll
        for (int k = 0; k < 4; k++) {
            int i = i0 + 16 * k;
            float c50 = fmaf((float)i, 300.0f / 63.0f, -150.0f);  // 50 * center_i
            float tu = fmaf(ur, 50.0f, -c50);
            float su = iy * frcp(fmaf(tu, tu, 1.0f));             // U
            float tv = fmaf(vr, 50.0f, -c50);
            float sv = frcp(fmaf(tv, tv, 1.0f));                  // V
            float tw = fmaf(wv, 50.0f, -c50);
            float sw = frcp(fmaf(tw, tw, 1.0f));                  // W
            s_sv[nb][p][i] = sv;
            s_w [nb][p][i] = sw;
            *(float2*)&s_su2 [nb][p][2 * i] = make_float2(su, su);
            float vi = iy * sv;
            *(float2*)&s_svi2[nb][p][2 * i] = make_float2(vi, vi);  // Vi
        }
    };

    // Prologue: fill buffer 0, prefetch round 1.
    stageB(0);
    pn += PB; fr = -1.f;
    if (owner && pn < ce) { fr = pr[pn]; fg = pg[pn]; fb = pbl[pn]; }
    __syncthreads();

    // Lane-fixed bases.
    const float* su2b  = &s_su2 [0][0][0] + 2 * row0;   // dup rows: 32B*rg + 128B*wg
    const float* svi2b = &s_svi2[0][0][0] + 2 * row0;
    const float* svb   = &s_sv  [0][0][0] + col0;       // natural col quads
    const float* wb    = &s_w   [0][0][0] + col0;

    for (int it = 0; it < nr; it++) {
        int cur = it & 1;
        if (it + 1 < nr) {
            stageB(cur ^ 1);
            pn += PB; fr = -1.f;
            if (owner && pn < ce) { fr = pr[pn]; fg = pg[pn]; fb = pbl[pn]; }
        }

        const float* su2p  = su2b  + cur * (PB * 128);
        const float* svi2p = svi2b + cur * (PB * 128);
        const float* svp   = svb   + cur * (PB * 64);
        const float* wp    = wb    + cur * (PB * 64);

        // Stage C: 8 pixels; 8 LDS.128 + 48 FFMA2 per pixel.
#pragma unroll
        for (int q = 0; q < PB; q++) {
            ulonglong2 u01 = *(const ulonglong2*)(su2p  + q * 128);      // dup U rows r0,r0+1
            ulonglong2 u23 = *(const ulonglong2*)(su2p  + q * 128 + 4);  // dup U rows r0+2,r0+3
            ulonglong2 x01 = *(const ulonglong2*)(svi2p + q * 128);      // dup Vi
            ulonglong2 x23 = *(const ulonglong2*)(svi2p + q * 128 + 4);
            ulonglong2 cv0 = *(const ulonglong2*)(svp + q * 64);         // V cols c0..c0+3
            ulonglong2 cv1 = *(const ulonglong2*)(svp + q * 64 + 4);     // V cols c0+4..c0+7
            ulonglong2 cw0 = *(const ulonglong2*)(wp  + q * 64);         // W cols c0..c0+3
            ulonglong2 cw1 = *(const ulonglong2*)(wp  + q * 64 + 4);     // W cols c0+4..c0+7

            unsigned long long rU [4] = { u01.x, u01.y, u23.x, u23.y };
            unsigned long long rVi[4] = { x01.x, x01.y, x23.x, x23.y };
            unsigned long long cV [4] = { cv0.x, cv0.y, cv1.x, cv1.y };
            unsigned long long cW [4] = { cw0.x, cw0.y, cw1.x, cw1.y };

#pragma unroll
            for (int k = 0; k < 4; k++) {
#pragma unroll
                for (int m = 0; m < 4; m++) {
                    FFMA2(accR[k][m], rU[k],  cV[m]);
                    FFMA2(accG[k][m], rU[k],  cW[m]);
                    FFMA2(accB[k][m], rVi[k], cW[m]);
                }
            }
        }
        __syncthreads();
    }

    // ---- Writeout: atomic reduce into global hist (reversals applied here) ----
    size_t basec = ((size_t)(img * 8 + b)) * 3 * 4096;
    float* hR = g_hist + basec;
    float* hG = g_hist + basec + 4096;
    float* hB = g_hist + basec + 8192;
#pragma unroll
    for (int k = 0; k < 4; k++) {
        int row  = row0 + k;
        int rofw = row * 64;              // forward row offset (R)
        int rofr = (63 - row) * 64;       // reversed row offset (G, B)
#pragma unroll
        for (int m = 0; m < 4; m++) {
            int c0 = col0 + 2 * m;
            atomicAdd(hR + rofw + c0,      plo(accR[k][m]));
            atomicAdd(hR + rofw + c0 + 1,  phi(accR[k][m]));
            atomicAdd(hG + rofr + c0,      plo(accG[k][m]));
            atomicAdd(hG + rofr + c0 + 1,  phi(accG[k][m]));
            atomicAdd(hB + rofr + 63 - c0, plo(accB[k][m]));
            atomicAdd(hB + rofr + 62 - c0, phi(accB[k][m]));
        }
    }
}

// ---------------------------------------------------------------------------
// Kernel 2: per-batch normalize + Hellinger-style distance
// ---------------------------------------------------------------------------
__global__ void loss_kernel() {
    int b = blockIdx.x;                     // 0..7
    const float* hx = g_hist + (size_t)b * 12288;         // img 0
    const float* hy = g_hist + (size_t)(8 + b) * 12288;   // img 1
    __shared__ float red[256];
    int tid = threadIdx.x;

    float sx = 0.f, sy = 0.f;
    for (int i = tid; i < 12288; i += 256) { sx += hx[i]; sy += hy[i]; }

    red[tid] = sx; __syncthreads();
    for (int s = 128; s > 0; s >>= 1) { if (tid < s) red[tid] += red[tid + s]; __syncthreads(); }
    float Tx = red[0]; __syncthreads();

    red[tid] = sy; __syncthreads();
    for (int s = 128; s > 0; s >>= 1) { if (tid < s) red[tid] += red[tid + s]; __syncthreads(); }
    float Ty = red[0]; __syncthreads();

    float ivx = 1.0f / Tx, ivy = 1.0f / Ty;
    float acc = 0.f;
    for (int i = tid; i < 12288; i += 256) {
        float d = sqrtf(hy[i] * ivy) - sqrtf(hx[i] * ivx);
        acc = fmaf(d, d, acc);
    }
    red[tid] = acc; __syncthreads();
    for (int s = 128; s > 0; s >>= 1) { if (tid < s) red[tid] += red[tid + s]; __syncthreads(); }
    if (tid == 0) g_hn[b] = sqrtf(red[0] * 0.5f);
}

// ---------------------------------------------------------------------------
// Kernel 3: mean over batch
// ---------------------------------------------------------------------------
__global__ void final_kernel(float* out) {
    if (threadIdx.x == 0) {
        float s = 0.f;
#pragma unroll
        for (int i = 0; i < 8; i++) s += g_hn[i];
        out[0] = s * 0.125f;
    }
}

// ---------------------------------------------------------------------------
extern "C" void kernel_launch(void* const* d_in, const int* in_sizes, int n_in,
                              void* d_out, int out_size) {
    const float* x = (const float*)d_in[0];
    const float* y = (const float*)d_in[1];

    const int SLICE = (HISTN + 2) / 3;
    zero_kernel<<<(SLICE + 255) / 256, 256>>>(0);
    zero_kernel<<<(SLICE + 255) / 256, 256>>>(SLICE);
    zero_kernel<<<(SLICE + 255) / 256, 256>>>(2 * SLICE);
    hist_kernel<<<16 * NCHUNK, 128>>>(x, y);
    loss_kernel<<<8, 256>>>();
    final_kernel<<<1, 32>>>((float*)d_out);
}

// round 14
// speedup vs baseline: 1.6222x; 1.0203x over previous
#include <cuda_runtime.h>

// Problem constants
#define NPIX   65536          // 256*256
#define DH     64             // histogram bins
#define PB     8              // pixels staged per round (8 px x 16 thr = 128)
#define NCHUNK 36             // pixel chunks per (img,b) -> 16*36 = 576 CTAs (~4/SM)
#define CPX    ((NPIX + NCHUNK - 1) / NCHUNK)
#define HISTN  (2 * 8 * 3 * DH * DH)

// Scratch (allocation-free rule: __device__ globals)
__device__ float g_hist[HISTN];   // [img][b][ch][64][64]
__device__ float g_hn[8];

__device__ __forceinline__ float frcp(float x) {
    float r; asm("rcp.approx.f32 %0, %1;" : "=f"(r) : "f"(x)); return r;
}
__device__ __forceinline__ float fsqrt_ap(float x) {
    float r; asm("sqrt.approx.f32 %0, %1;" : "=f"(r) : "f"(x)); return r;
}
__device__ __forceinline__ float plo(unsigned long long v) {
    return __uint_as_float((unsigned int)(v & 0xffffffffull));
}
__device__ __forceinline__ float phi(unsigned long long v) {
    return __uint_as_float((unsigned int)(v >> 32));
}

#define FFMA2(acc, a, b) asm("fma.rn.f32x2 %0, %1, %2, %0;" : "+l"(acc) : "l"(a), "l"(b))
// Build a (v, v) broadcast pair in the ALU pipe (frees the LSU from dup-array loads).
#define PACK2(d, s)      asm("mov.b64 %0, {%1, %1};" : "=l"(d) : "f"(s))

// ---------------------------------------------------------------------------
// Kernel 0: zero a slice of the histogram scratch (3 launches keep hist_kernel
// at global launch index 5 for the ncu -s 5 -c 1 capture).
// ---------------------------------------------------------------------------
__global__ void zero_kernel(int off) {
    int i = off + blockIdx.x * blockDim.x + threadIdx.x;
    if (i < HISTN) g_hist[i] = 0.0f;
}

// ---------------------------------------------------------------------------
// Kernel 1: histogram accumulation.
// 128-thread CTAs (4 warps), target 4 CTAs/SM. The 4 warps jointly cover the
// full 64x64 hist: warp wg (0..3) x lane (rg=l>>3, cg=l&7) owns rows
// {16wg+4rg .. +3} x cols {8cg .. 8cg+7} -> per-lane tile 4x8 x 3 channels =
// 48 packed f32x2 accumulators; 48 FFMA2 per pixel.
// SMEM traffic per lane-pixel: 2x LDS.64 rows (U,Vi natural scalars, packed
// to (v,v) pairs via mov.b64 in the ALU pipe) + 4x LDS.128 cols = 24 LSU cyc
// == 24 fma cyc -> balanced pipes (R9 dup-row arrays cost 32 LSU cyc).
//
// With U = iy*rbf(ur), Vi = iy*rbf(vr), V = rbf(vr), W = rbf(lg-lb):
//   accR[r][c] = sum U[r]*V[c]  = hist_r[r][c]
//   accG[r][c] = sum U[r]*W[c]  = hist_g[63-r][c]     (reverse rows at writeout)
//   accB[r][c] = sum Vi[r]*W[c] = hist_b[63-r][63-c]  (reverse both at writeout)
//
// Single __syncthreads per 8-pixel round (double-buffered SMEM; Stage B fills
// buf[nxt] while Stage C consumes buf[cur]; pixel scalars broadcast in-warp).
// ---------------------------------------------------------------------------
__global__ void __launch_bounds__(128, 4)
hist_kernel(const float* __restrict__ x, const float* __restrict__ y) {
    int combo = blockIdx.x / NCHUNK;
    int chunk = blockIdx.x % NCHUNK;
    int img = combo >> 3;
    int b   = combo & 7;
    const float* src = img ? y : x;
    const float* pr  = src + (size_t)(b * 3 + 0) * NPIX;
    const float* pg  = src + (size_t)(b * 3 + 1) * NPIX;
    const float* pbl = src + (size_t)(b * 3 + 2) * NPIX;

    int cs = chunk * CPX;
    int ce = cs + CPX; if (ce > NPIX) ce = NPIX;

    // Double-buffered SMEM, all natural (scalar) order -- no dup arrays.
    __shared__ float s_su [2][PB][64];   // U  = iy*rbf(ur)
    __shared__ float s_svi[2][PB][64];   // Vi = iy*rbf(vr)
    __shared__ float s_sv [2][PB][64];   // V  = rbf(vr)
    __shared__ float s_w  [2][PB][64];   // W  = rbf(lg-lb)
    __shared__ float4 s_px[PB];          // (ur, vr, w, iy) -- single buffer is fine:
                                         // consumed by Stage B before next overwrite (sync'd)

    const int tid = threadIdx.x;
    const int wg  = tid >> 5;          // warp 0..3
    const int l   = tid & 31;
    const int rg  = l >> 3;            // 0..3
    const int cg  = l & 7;             // 0..7
    const int row0 = 16 * wg + 4 * rg; // this lane's 4 rows
    const int col0 = 8 * cg;           // this lane's 8 cols
    const int p   = tid >> 4;          // pixel-in-round this thread evaluates (Stage B)
    const int i0  = tid & 15;          // bin base (bins i0, i0+16, i0+32, i0+48)
    const bool owner = (i0 == 0);
    const int srcln  = l & 16;         // owner lane within warp (0 or 16)

    // acc[r][cp]: r = 0..3, cp = col pair 0..3
    unsigned long long accR[4][4], accG[4][4], accB[4][4];
#pragma unroll
    for (int k = 0; k < 4; k++)
#pragma unroll
        for (int m = 0; m < 4; m++) { accR[k][m] = 0ull; accG[k][m] = 0ull; accB[k][m] = 0ull; }

    const int nr = (ce - cs + PB - 1) / PB;

    // Owner-lane prefetch registers; fr = -1 marks an invalid (pad) pixel.
    int pn = cs + p;
    float fr = -1.f, fg = 0.f, fb = 0.f;
    if (owner && pn < ce) { fr = pr[pn]; fg = pg[pn]; fb = pbl[pn]; }

    // Stage B: evaluate RBF rows for this thread's pixel into buffer nb.
    auto stageB = [&](int nb) {
        float r0 = __shfl_sync(0xffffffffu, fr, srcln);
        float g0 = __shfl_sync(0xffffffffu, fg, srcln);
        float b0 = __shfl_sync(0xffffffffu, fb, srcln);
        bool valid = (r0 >= 0.f);
        float r  = valid ? r0 + 1e-6f : 1.0f;
        float g  = valid ? g0 + 1e-6f : 1.0f;
        float bb = valid ? b0 + 1e-6f : 1.0f;
        float lr_ = __logf(r), lg_ = __logf(g), lb_ = __logf(bb);
        float ur = lr_ - lg_;
        float vr = lr_ - lb_;
        float wv = lg_ - lb_;
        float iy = valid ? fsqrt_ap(fmaf(r, r, fmaf(g, g, bb * bb))) : 0.f;
#pragma unroll
        for (int k = 0; k < 4; k++) {
            int i = i0 + 16 * k;
            float c50 = fmaf((float)i, 300.0f / 63.0f, -150.0f);  // 50 * center_i
            float tu = fmaf(ur, 50.0f, -c50);
            float su = iy * frcp(fmaf(tu, tu, 1.0f));             // U
            float tv = fmaf(vr, 50.0f, -c50);
            float sv = frcp(fmaf(tv, tv, 1.0f));                  // V
            float tw = fmaf(wv, 50.0f, -c50);
            float sw = frcp(fmaf(tw, tw, 1.0f));                  // W
            s_su [nb][p][i] = su;
            s_svi[nb][p][i] = iy * sv;                            // Vi
            s_sv [nb][p][i] = sv;
            s_w  [nb][p][i] = sw;
        }
    };

    // Prologue: fill buffer 0, prefetch round 1.
    stageB(0);
    pn += PB; fr = -1.f;
    if (owner && pn < ce) { fr = pr[pn]; fg = pg[pn]; fb = pbl[pn]; }
    __syncthreads();

    // Lane-fixed bases (natural order; row0/col0 are multiples of 4 -> aligned).
    const float* sub  = &s_su [0][0][0] + row0;
    const float* svib = &s_svi[0][0][0] + row0;
    const float* svb  = &s_sv [0][0][0] + col0;
    const float* wb   = &s_w  [0][0][0] + col0;

    for (int it = 0; it < nr; it++) {
        int cur = it & 1;
        if (it + 1 < nr) {
            stageB(cur ^ 1);
            pn += PB; fr = -1.f;
            if (owner && pn < ce) { fr = pr[pn]; fg = pg[pn]; fb = pbl[pn]; }
        }

        const float* sup  = sub  + cur * (PB * 64);
        const float* svip = svib + cur * (PB * 64);
        const float* svp  = svb  + cur * (PB * 64);
        const float* wp   = wb   + cur * (PB * 64);

        // Stage C: 8 pixels; 4 LDS.64 + 4 LDS.128 + 8 PACK + 48 FFMA2 per pixel.
#pragma unroll
        for (int q = 0; q < PB; q++) {
            float2 ua = *(const float2*)(sup  + q * 64);        // U rows r0, r0+1
            float2 ub = *(const float2*)(sup  + q * 64 + 2);    // U rows r0+2, r0+3
            float2 xa = *(const float2*)(svip + q * 64);        // Vi rows
            float2 xb = *(const float2*)(svip + q * 64 + 2);
            ulonglong2 cv0 = *(const ulonglong2*)(svp + q * 64);       // V cols c0..c0+3
            ulonglong2 cv1 = *(const ulonglong2*)(svp + q * 64 + 4);   // V cols c0+4..c0+7
            ulonglong2 cw0 = *(const ulonglong2*)(wp  + q * 64);       // W cols c0..c0+3
            ulonglong2 cw1 = *(const ulonglong2*)(wp  + q * 64 + 4);   // W cols c0+4..c0+7

            unsigned long long rU[4], rVi[4];
            PACK2(rU[0],  ua.x); PACK2(rU[1],  ua.y); PACK2(rU[2],  ub.x); PACK2(rU[3],  ub.y);
            PACK2(rVi[0], xa.x); PACK2(rVi[1], xa.y); PACK2(rVi[2], xb.x); PACK2(rVi[3], xb.y);

            unsigned long long cV[4] = { cv0.x, cv0.y, cv1.x, cv1.y };
            unsigned long long cW[4] = { cw0.x, cw0.y, cw1.x, cw1.y };

#pragma unroll
            for (int k = 0; k < 4; k++) {
#pragma unroll
                for (int m = 0; m < 4; m++) {
                    FFMA2(accR[k][m], rU[k],  cV[m]);
                    FFMA2(accG[k][m], rU[k],  cW[m]);
                    FFMA2(accB[k][m], rVi[k], cW[m]);
                }
            }
        }
        __syncthreads();
    }

    // ---- Writeout: atomic reduce into global hist (reversals applied here) ----
    size_t basec = ((size_t)(img * 8 + b)) * 3 * 4096;
    float* hR = g_hist + basec;
    float* hG = g_hist + basec + 4096;
    float* hB = g_hist + basec + 8192;
#pragma unroll
    for (int k = 0; k < 4; k++) {
        int row  = row0 + k;
        int rofw = row * 64;              // forward row offset (R)
        int rofr = (63 - row) * 64;       // reversed row offset (G, B)
#pragma unroll
        for (int m = 0; m < 4; m++) {
            int c0 = col0 + 2 * m;
            atomicAdd(hR + rofw + c0,      plo(accR[k][m]));
            atomicAdd(hR + rofw + c0 + 1,  phi(accR[k][m]));
            atomicAdd(hG + rofr + c0,      plo(accG[k][m]));
            atomicAdd(hG + rofr + c0 + 1,  phi(accG[k][m]));
            atomicAdd(hB + rofr + 63 - c0, plo(accB[k][m]));
            atomicAdd(hB + rofr + 62 - c0, phi(accB[k][m]));
        }
    }
}

// ---------------------------------------------------------------------------
// Kernel 2: per-batch normalize + Hellinger-style distance
// ---------------------------------------------------------------------------
__global__ void loss_kernel() {
    int b = blockIdx.x;                     // 0..7
    const float* hx = g_hist + (size_t)b * 12288;         // img 0
    const float* hy = g_hist + (size_t)(8 + b) * 12288;   // img 1
    __shared__ float red[256];
    int tid = threadIdx.x;

    float sx = 0.f, sy = 0.f;
    for (int i = tid; i < 12288; i += 256) { sx += hx[i]; sy += hy[i]; }

    red[tid] = sx; __syncthreads();
    for (int s = 128; s > 0; s >>= 1) { if (tid < s) red[tid] += red[tid + s]; __syncthreads(); }
    float Tx = red[0]; __syncthreads();

    red[tid] = sy; __syncthreads();
    for (int s = 128; s > 0; s >>= 1) { if (tid < s) red[tid] += red[tid + s]; __syncthreads(); }
    float Ty = red[0]; __syncthreads();

    float ivx = 1.0f / Tx, ivy = 1.0f / Ty;
    float acc = 0.f;
    for (int i = tid; i < 12288; i += 256) {
        float d = sqrtf(hy[i] * ivy) - sqrtf(hx[i] * ivx);
        acc = fmaf(d, d, acc);
    }
    red[tid] = acc; __syncthreads();
    for (int s = 128; s > 0; s >>= 1) { if (tid < s) red[tid] += red[tid + s]; __syncthreads(); }
    if (tid == 0) g_hn[b] = sqrtf(red[0] * 0.5f);
}

// ---------------------------------------------------------------------------
// Kernel 3: mean over batch
// ---------------------------------------------------------------------------
__global__ void final_kernel(float* out) {
    if (threadIdx.x == 0) {
        float s = 0.f;
#pragma unroll
        for (int i = 0; i < 8; i++) s += g_hn[i];
        out[0] = s * 0.125f;
    }
}

// ---------------------------------------------------------------------------
extern "C" void kernel_launch(void* const* d_in, const int* in_sizes, int n_in,
                              void* d_out, int out_size) {
    const float* x = (const float*)d_in[0];
    const float* y = (const float*)d_in[1];

    const int SLICE = (HISTN + 2) / 3;
    zero_kernel<<<(SLICE + 255) / 256, 256>>>(0);
    zero_kernel<<<(SLICE + 255) / 256, 256>>>(SLICE);
    zero_kernel<<<(SLICE + 255) / 256, 256>>>(2 * SLICE);
    hist_kernel<<<16 * NCHUNK, 128>>>(x, y);
    loss_kernel<<<8, 256>>>();
    final_kernel<<<1, 32>>>((float*)d_out);
}